// round 8
// baseline (speedup 1.0000x reference)
#include <cuda_runtime.h>

#define FULL 0xFFFFFFFFu
#define NCAM 6
#define LWIN 36
#define QN   1536
#define KN   384
#define HL   144
#define DIMF 128
#define KEEPQ 1152
#define TOPK  96
#define SCALE_F 0.17677669529663687f

__device__ float QH[HL * QN * 32];
__device__ float KH[HL * KN * 32];
__device__ float VH[HL * KN * 32];
__device__ float AO[HL * QN * 32];
__device__ float SAL[HL * QN];
__device__ unsigned char QKEEP[HL * QN];
__device__ float PMEAN[HL * 32];

// ---------------------------------------------------------------------------
// Kernel 1: window rearrange + LayerNorm + 128x128 projection, warp per token.
// which: 0 -> QH (+SAL), 1 -> KH, 2 -> VH.
// ---------------------------------------------------------------------------
__global__ void proj_kernel(const float* __restrict__ in,
                            const float* __restrict__ gamma,
                            const float* __restrict__ beta,
                            const float* __restrict__ W,
                            const float* __restrict__ bias,
                            int tokPerL, int wsz, int which)
{
    extern __shared__ float Wsh[];
    for (int i = threadIdx.x; i < 128 * 128 / 4; i += blockDim.x)
        ((float4*)Wsh)[i] = ((const float4*)W)[i];
    __syncthreads();

    float* out = (which == 0) ? QH : (which == 1) ? KH : VH;

    const int lane = threadIdx.x & 31;
    const int wid  = threadIdx.x >> 5;
    const int nwarps = (blockDim.x >> 5) * gridDim.x;
    int gw = blockIdx.x * (blockDim.x >> 5) + wid;
    const float4* Wsh4 = (const float4*)Wsh;

    const float4 gm = ((const float4*)gamma)[lane];
    const float4 bt = ((const float4*)beta)[lane];
    const float4 bi = ((const float4*)bias)[lane];
    const int ww = wsz * wsz;
    const int h = lane >> 3, dh = (lane & 7) * 4;
    const int nTok = LWIN * tokPerL;

    for (int o = gw; o < nTok; o += nwarps) {
        int l = o / tokPerL, t = o - l * tokPerL;
        int n = t / ww, r = t - n * ww;
        int w1 = r / wsz, w2 = r - w1 * wsz;
        int x = l / 6, y = l - x * 6;
        int inIdx = ((((n * 6 + x) * 6 + y) * wsz + w1) * wsz + w2) * DIMF;

        float4 xv = ((const float4*)(in + inIdx))[lane];
        float s  = xv.x + xv.y + xv.z + xv.w;
        float ss = xv.x*xv.x + xv.y*xv.y + xv.z*xv.z + xv.w*xv.w;
        #pragma unroll
        for (int off = 16; off > 0; off >>= 1) {
            s  += __shfl_xor_sync(FULL, s,  off);
            ss += __shfl_xor_sync(FULL, ss, off);
        }
        float mu   = s * (1.f / 128.f);
        float var  = ss * (1.f / 128.f) - mu * mu;
        float rstd = rsqrtf(var + 1e-5f);

        float xn[4];
        xn[0] = (xv.x - mu) * rstd * gm.x + bt.x;
        xn[1] = (xv.y - mu) * rstd * gm.y + bt.y;
        xn[2] = (xv.z - mu) * rstd * gm.z + bt.z;
        xn[3] = (xv.w - mu) * rstd * gm.w + bt.w;

        float4 acc = bi;
        #pragma unroll 8
        for (int sl = 0; sl < 32; ++sl) {
            #pragma unroll
            for (int jj = 0; jj < 4; ++jj) {
                float xk = __shfl_sync(FULL, xn[jj], sl);
                float4 w = Wsh4[(sl * 4 + jj) * 32 + lane];
                acc.x = fmaf(xk, w.x, acc.x);
                acc.y = fmaf(xk, w.y, acc.y);
                acc.z = fmaf(xk, w.z, acc.z);
                acc.w = fmaf(xk, w.w, acc.w);
            }
        }
        ((float4*)(out + ((h * LWIN + l) * tokPerL + t) * 32 + dh))[0] = acc;

        if (which == 0) {
            float sq = acc.x*acc.x + acc.y*acc.y + acc.z*acc.z + acc.w*acc.w;
            sq += __shfl_down_sync(FULL, sq, 4, 8);
            sq += __shfl_down_sync(FULL, sq, 2, 8);
            sq += __shfl_down_sync(FULL, sq, 1, 8);
            if ((lane & 7) == 0)
                SAL[(h * LWIN + l) * tokPerL + t] = sq;
        }
    }
}

// ---------------------------------------------------------------------------
// Kernel 2: keep top-1152 of 1536 saliencies per (h,l).
// Keys in registers (6 contiguous/thread), early-exit bitwise search,
// parallel prefix-scan tie-break (no serial tail).
// ---------------------------------------------------------------------------
__global__ void qkeep_kernel()
{
    __shared__ unsigned keys[QN];
    __shared__ int cnts[2];
    __shared__ int wse[8];
    __shared__ int gtTot;
    const int tid = threadIdx.x, lane = tid & 31, wid = tid >> 5;
    const int row = blockIdx.x;
    const int base = tid * 6;

    for (int i = tid; i < QN; i += 256) {
        unsigned u = __float_as_uint(SAL[row * QN + i]);
        keys[i] = (u & 0x80000000u) ? ~u : (u | 0x80000000u);
    }
    if (tid < 2) cnts[tid] = 0;
    if (tid == 2) gtTot = 0;
    __syncthreads();

    const unsigned k0 = keys[base+0], k1 = keys[base+1], k2 = keys[base+2],
                   k3 = keys[base+3], k4 = keys[base+4], k5 = keys[base+5];

    unsigned T = 0;
    int exact = 0;
    for (int b = 31; b >= 0; --b) {
        unsigned cand = T | (1u << b);
        unsigned c = (k0>=cand)+(k1>=cand)+(k2>=cand)+(k3>=cand)+(k4>=cand)+(k5>=cand);
        c = __reduce_add_sync(FULL, c);
        if (lane == 0) atomicAdd(&cnts[b & 1], (int)c);
        __syncthreads();
        int tot = cnts[b & 1];
        if (tid == 0) cnts[(b & 1) ^ 1] = 0;
        if (tot >= KEEPQ) { T = cand; if (tot == KEEPQ) exact = 1; }
        __syncthreads();
        if (exact) break;
    }

    unsigned char* Qp = &QKEEP[row * QN + base];
    if (exact) {
        Qp[0] = (k0 >= T); Qp[1] = (k1 >= T); Qp[2] = (k2 >= T);
        Qp[3] = (k3 >= T); Qp[4] = (k4 >= T); Qp[5] = (k5 >= T);
    } else {
        int gtc = (k0>T)+(k1>T)+(k2>T)+(k3>T)+(k4>T)+(k5>T);
        int e0 = (k0==T), e1 = (k1==T), e2 = (k2==T),
            e3 = (k3==T), e4 = (k4==T), e5 = (k5==T);
        int eqc = e0+e1+e2+e3+e4+e5;
        unsigned g = __reduce_add_sync(FULL, (unsigned)gtc);
        if (lane == 0) atomicAdd(&gtTot, (int)g);
        int incl = eqc;
        #pragma unroll
        for (int off = 1; off < 32; off <<= 1) {
            int n = __shfl_up_sync(FULL, incl, off);
            if (lane >= off) incl += n;
        }
        if (lane == 31) wse[wid] = incl;
        __syncthreads();
        int before = 0;
        for (int w = 0; w < wid; ++w) before += wse[w];
        int myExcl = before + incl - eqc;
        int r = (KEEPQ - gtTot) - myExcl;   // keep my eq elems with local rank < r
        int cum = 0;
        Qp[0] = (k0>T) || (e0 && cum < r); cum += e0;
        Qp[1] = (k1>T) || (e1 && cum < r); cum += e1;
        Qp[2] = (k2>T) || (e2 && cum < r); cum += e2;
        Qp[3] = (k3>T) || (e3 && cum < r); cum += e3;
        Qp[4] = (k4>T) || (e4 && cum < r); cum += e4;
        Qp[5] = (k5>T) || (e5 && cum < r);
    }
}

// ---------------------------------------------------------------------------
// Kernel 3: pruned-query result = mean(VH[0:96]) per (h,l).
// ---------------------------------------------------------------------------
__global__ void pmean_kernel()
{
    const int hl = blockIdx.x, d = threadIdx.x;
    float s = 0.f;
    for (int k = 0; k < TOPK; ++k) s += VH[(hl * KN + k) * 32 + d];
    PMEAN[hl * 32 + d] = s * (1.f / (float)TOPK);
}

// ---------------------------------------------------------------------------
// Kernel 4: attention. One block per (h,l). Warp handles 8 queries; 12 k/lane.
// Pruned queries skipped everywhere (warp-uniform). Early-exit top-96.
// ---------------------------------------------------------------------------
__global__ void __launch_bounds__(256, 1) attn_kernel()
{
    extern __shared__ float sm[];
    float* Kt = sm;              // 32 x 388
    float* Vt = sm + 12416;      // 32 x 388
    float* AB = sm + 24832;      // 8 warps * 8 q * 384 = 24576 floats

    const int hl = blockIdx.x;
    const int tid = threadIdx.x, lane = tid & 31, wid = tid >> 5;

    for (int i = tid; i < KN * 32; i += 256) {
        int k = i >> 5, d = i & 31;
        Kt[d * 388 + k] = KH[hl * (KN * 32) + i];
        Vt[d * 388 + k] = VH[hl * (KN * 32) + i];
    }
    __syncthreads();

    const float pm = PMEAN[hl * 32 + lane];
    float* myAB = AB + wid * 3072;
    const unsigned lt = (1u << lane) - 1u;

    for (int g = wid; g < QN / 8; g += 8) {
        const int q0 = g * 8;
        float qreg[8]; int kp[8];
        #pragma unroll
        for (int qq = 0; qq < 8; ++qq) {
            qreg[qq] = QH[(hl * QN + q0 + qq) * 32 + lane] * SCALE_F;
            kp[qq]   = QKEEP[hl * QN + q0 + qq];
        }

        float acc[8][12];
        #pragma unroll
        for (int qq = 0; qq < 8; ++qq)
            #pragma unroll
            for (int i = 0; i < 12; ++i) acc[qq][i] = 0.f;

        // QK^T: lane owns k = lane*12 .. lane*12+11
        #pragma unroll 2
        for (int d = 0; d < 32; ++d) {
            const float4* kr = (const float4*)(Kt + d * 388 + lane * 12);
            float4 c0 = kr[0], c1 = kr[1], c2 = kr[2];
            float kv[12] = {c0.x,c0.y,c0.z,c0.w,c1.x,c1.y,c1.z,c1.w,c2.x,c2.y,c2.z,c2.w};
            #pragma unroll
            for (int qq = 0; qq < 8; ++qq) {
                if (kp[qq]) {                       // warp-uniform
                    float qb = __shfl_sync(FULL, qreg[qq], d);
                    #pragma unroll
                    for (int i = 0; i < 12; ++i)
                        acc[qq][i] = fmaf(qb, kv[i], acc[qq][i]);
                }
            }
        }

        // top-96 + softmax per kept query
        #pragma unroll
        for (int qq = 0; qq < 8; ++qq) {
            if (!kp[qq]) continue;                  // warp-uniform
            unsigned us[12];
            #pragma unroll
            for (int i = 0; i < 12; ++i) {
                unsigned u = __float_as_uint(acc[qq][i]);
                us[i] = (u & 0x80000000u) ? ~u : (u | 0x80000000u);
            }
            unsigned T = 0; bool exact = false;
            for (int b = 31; b >= 0; --b) {
                unsigned cand = T | (1u << b);
                unsigned c = 0;
                #pragma unroll
                for (int i = 0; i < 12; ++i) c += (us[i] >= cand) ? 1u : 0u;
                c = __reduce_add_sync(FULL, c);
                if (c >= (unsigned)TOPK) {
                    T = cand;
                    if (c == (unsigned)TOPK) { exact = true; break; }
                }
            }
            bool keep[12];
            if (exact) {
                #pragma unroll
                for (int i = 0; i < 12; ++i) keep[i] = (us[i] >= T);
            } else {
                unsigned cg = 0;
                #pragma unroll
                for (int i = 0; i < 12; ++i) cg += (us[i] > T) ? 1u : 0u;
                cg = __reduce_add_sync(FULL, cg);
                int rem = (int)TOPK - (int)cg;
                int pre = 0;
                #pragma unroll
                for (int i = 0; i < 12; ++i) {
                    unsigned m = __ballot_sync(FULL, us[i] == T);
                    pre += __popc(m & lt);
                }
                int cum = 0;
                #pragma unroll
                for (int i = 0; i < 12; ++i) {
                    bool eq = (us[i] == T);
                    keep[i] = (us[i] > T) || (eq && (pre + cum) < rem);
                    cum += eq ? 1 : 0;
                }
            }
            float mx = acc[qq][0];
            #pragma unroll
            for (int i = 1; i < 12; ++i) mx = fmaxf(mx, acc[qq][i]);
            #pragma unroll
            for (int off = 16; off > 0; off >>= 1)
                mx = fmaxf(mx, __shfl_xor_sync(FULL, mx, off));

            float e[12]; float ssum = 0.f;
            #pragma unroll
            for (int i = 0; i < 12; ++i) {
                float ev = keep[i] ? __expf(acc[qq][i] - mx) : 0.f;
                e[i] = ev; ssum += ev;
            }
            #pragma unroll
            for (int off = 16; off > 0; off >>= 1)
                ssum += __shfl_xor_sync(FULL, ssum, off);
            float inv = 1.f / ssum;
            float4* dst = (float4*)(myAB + qq * 384 + lane * 12);
            dst[0] = make_float4(e[0]*inv, e[1]*inv, e[2]*inv,  e[3]*inv);
            dst[1] = make_float4(e[4]*inv, e[5]*inv, e[6]*inv,  e[7]*inv);
            dst[2] = make_float4(e[8]*inv, e[9]*inv, e[10]*inv, e[11]*inv);
        }
        __syncwarp();

        // AV: lane = output dim; V load amortized across 8 queries
        float o[8];
        #pragma unroll
        for (int qq = 0; qq < 8; ++qq) o[qq] = 0.f;
        const float4* vr = (const float4*)(Vt + lane * 388);
        #pragma unroll 4
        for (int c = 0; c < KN / 4; ++c) {
            float4 v4 = vr[c];
            #pragma unroll
            for (int qq = 0; qq < 8; ++qq) {
                if (kp[qq]) {                       // warp-uniform
                    float4 a = ((const float4*)(myAB + qq * 384))[c];
                    o[qq] += a.x*v4.x + a.y*v4.y + a.z*v4.z + a.w*v4.w;
                }
            }
        }
        __syncwarp();

        #pragma unroll
        for (int qq = 0; qq < 8; ++qq)
            AO[(hl * QN + q0 + qq) * 32 + lane] = kp[qq] ? o[qq] : pm;
    }
}

// ---------------------------------------------------------------------------
// Kernel 5: camera-mean -> output projection -> + bp + skip. Warp per token.
// ---------------------------------------------------------------------------
__global__ void final_kernel(const float* __restrict__ skip,
                             const float* __restrict__ Wp,
                             const float* __restrict__ bp,
                             float* __restrict__ outp)
{
    extern __shared__ float Wsh[];
    for (int i = threadIdx.x; i < 128 * 128 / 4; i += blockDim.x)
        ((float4*)Wsh)[i] = ((const float4*)Wp)[i];
    __syncthreads();

    const int lane = threadIdx.x & 31;
    const int wid  = threadIdx.x >> 5;
    const int nwarps = (blockDim.x >> 5) * gridDim.x;
    int gw = blockIdx.x * (blockDim.x >> 5) + wid;
    const float4* Wsh4 = (const float4*)Wsh;
    const float4 bi = ((const float4*)bp)[lane];
    const int h = lane >> 3, dbase = (lane & 7) * 4;

    for (int o = gw; o < LWIN * 256; o += nwarps) {
        int l = o >> 8, rr = o & 255;
        float4 ab = make_float4(0.f,0.f,0.f,0.f);
        #pragma unroll
        for (int n = 0; n < NCAM; ++n) {
            float4 t = ((const float4*)(AO + ((h * LWIN + l) * QN + n * 256 + rr) * 32 + dbase))[0];
            ab.x += t.x; ab.y += t.y; ab.z += t.z; ab.w += t.w;
        }
        const float inv6 = 1.f / 6.f;
        float xn[4] = {ab.x*inv6, ab.y*inv6, ab.z*inv6, ab.w*inv6};

        float4 acc = bi;
        #pragma unroll 8
        for (int sl = 0; sl < 32; ++sl) {
            #pragma unroll
            for (int jj = 0; jj < 4; ++jj) {
                float xk = __shfl_sync(FULL, xn[jj], sl);
                float4 w = Wsh4[(sl * 4 + jj) * 32 + lane];
                acc.x = fmaf(xk, w.x, acc.x);
                acc.y = fmaf(xk, w.y, acc.y);
                acc.z = fmaf(xk, w.z, acc.z);
                acc.w = fmaf(xk, w.w, acc.w);
            }
        }
        float4 sk = ((const float4*)(skip + o * DIMF))[lane];
        acc.x += sk.x; acc.y += sk.y; acc.z += sk.z; acc.w += sk.w;
        ((float4*)(outp + o * DIMF))[lane] = acc;
    }
}

// ---------------------------------------------------------------------------
// Inputs: 0 q, 1 k, 2 v, 3 skip, 4 logit_bias (dead), 5 g_q, 6 b_q, 7 g_k,
// 8 b_k, 9 g_v, 10 b_v, 11 Wq, 12 bq, 13 Wk, 14 bk, 15 Wv, 16 bv, 17 Wp, 18 bp
// ---------------------------------------------------------------------------
extern "C" void kernel_launch(void* const* d_in, const int* in_sizes, int n_in,
                              void* d_out, int out_size)
{
    const float* q    = (const float*)d_in[0];
    const float* k    = (const float*)d_in[1];
    const float* v    = (const float*)d_in[2];
    const float* skip = (const float*)d_in[3];
    const float* g_q  = (const float*)d_in[5];
    const float* b_q  = (const float*)d_in[6];
    const float* g_k  = (const float*)d_in[7];
    const float* b_k  = (const float*)d_in[8];
    const float* g_v  = (const float*)d_in[9];
    const float* b_v  = (const float*)d_in[10];
    const float* Wq   = (const float*)d_in[11];
    const float* bq   = (const float*)d_in[12];
    const float* Wk   = (const float*)d_in[13];
    const float* bk   = (const float*)d_in[14];
    const float* Wv   = (const float*)d_in[15];
    const float* bv   = (const float*)d_in[16];
    const float* Wp   = (const float*)d_in[17];
    const float* bp   = (const float*)d_in[18];
    float* outp = (float*)d_out;

    cudaFuncSetAttribute(proj_kernel,  cudaFuncAttributeMaxDynamicSharedMemorySize, 65536);
    cudaFuncSetAttribute(attn_kernel,  cudaFuncAttributeMaxDynamicSharedMemorySize, 197632);
    cudaFuncSetAttribute(final_kernel, cudaFuncAttributeMaxDynamicSharedMemorySize, 65536);

    proj_kernel<<<148, 256, 65536>>>(q, g_q, b_q, Wq, bq, QN, 16, 0);
    proj_kernel<<<148, 256, 65536>>>(k, g_k, b_k, Wk, bk, KN, 8, 1);
    proj_kernel<<<148, 256, 65536>>>(v, g_v, b_v, Wv, bv, KN, 8, 2);
    qkeep_kernel<<<HL, 256>>>();
    pmean_kernel<<<HL, 32>>>();
    attn_kernel<<<HL, 256, 197632>>>();
    final_kernel<<<148, 256, 65536>>>(skip, Wp, bp, outp);
}

// round 11
// speedup vs baseline: 1.3735x; 1.3735x over previous
#include <cuda_runtime.h>

#define FULL 0xFFFFFFFFu
#define NCAM 6
#define LWIN 36
#define QN   1536
#define KN   384
#define HL   144
#define DIMF 128
#define KEEPQ 1152
#define TOPK  96
#define SCALE_F 0.17677669529663687f

__device__ float QH[HL * QN * 32];
__device__ float KH[HL * KN * 32];
__device__ float VH[HL * KN * 32];
__device__ float AO[HL * QN * 32];
__device__ float SAL[HL * QN];
__device__ unsigned char QKEEP[HL * QN];
__device__ float PMEAN[HL * 32];

__device__ __forceinline__ unsigned f2key(float f) {
    unsigned u = __float_as_uint(f);
    return (u & 0x80000000u) ? ~u : (u | 0x80000000u);
}
__device__ __forceinline__ float key2f(unsigned k) {
    return __uint_as_float((k & 0x80000000u) ? (k ^ 0x80000000u) : ~k);
}

// ---------------------------------------------------------------------------
// Kernel 1: window rearrange + LayerNorm + 128x128 projection, warp per token.
// which: 0 -> QH (+SAL), 1 -> KH, 2 -> VH.
// ---------------------------------------------------------------------------
__global__ void proj_kernel(const float* __restrict__ in,
                            const float* __restrict__ gamma,
                            const float* __restrict__ beta,
                            const float* __restrict__ W,
                            const float* __restrict__ bias,
                            int tokPerL, int wsz, int which)
{
    extern __shared__ float Wsh[];
    for (int i = threadIdx.x; i < 128 * 128 / 4; i += blockDim.x)
        ((float4*)Wsh)[i] = ((const float4*)W)[i];
    __syncthreads();

    float* out = (which == 0) ? QH : (which == 1) ? KH : VH;

    const int lane = threadIdx.x & 31;
    const int wid  = threadIdx.x >> 5;
    const int nwarps = (blockDim.x >> 5) * gridDim.x;
    int gw = blockIdx.x * (blockDim.x >> 5) + wid;
    const float4* Wsh4 = (const float4*)Wsh;

    const float4 gm = ((const float4*)gamma)[lane];
    const float4 bt = ((const float4*)beta)[lane];
    const float4 bi = ((const float4*)bias)[lane];
    const int ww = wsz * wsz;
    const int h = lane >> 3, dh = (lane & 7) * 4;
    const int nTok = LWIN * tokPerL;

    for (int o = gw; o < nTok; o += nwarps) {
        int l = o / tokPerL, t = o - l * tokPerL;
        int n = t / ww, r = t - n * ww;
        int w1 = r / wsz, w2 = r - w1 * wsz;
        int x = l / 6, y = l - x * 6;
        int inIdx = ((((n * 6 + x) * 6 + y) * wsz + w1) * wsz + w2) * DIMF;

        float4 xv = ((const float4*)(in + inIdx))[lane];
        float s  = xv.x + xv.y + xv.z + xv.w;
        float ss = xv.x*xv.x + xv.y*xv.y + xv.z*xv.z + xv.w*xv.w;
        #pragma unroll
        for (int off = 16; off > 0; off >>= 1) {
            s  += __shfl_xor_sync(FULL, s,  off);
            ss += __shfl_xor_sync(FULL, ss, off);
        }
        float mu   = s * (1.f / 128.f);
        float var  = ss * (1.f / 128.f) - mu * mu;
        float rstd = rsqrtf(var + 1e-5f);

        float xn[4];
        xn[0] = (xv.x - mu) * rstd * gm.x + bt.x;
        xn[1] = (xv.y - mu) * rstd * gm.y + bt.y;
        xn[2] = (xv.z - mu) * rstd * gm.z + bt.z;
        xn[3] = (xv.w - mu) * rstd * gm.w + bt.w;

        float4 acc = bi;
        #pragma unroll 8
        for (int sl = 0; sl < 32; ++sl) {
            #pragma unroll
            for (int jj = 0; jj < 4; ++jj) {
                float xk = __shfl_sync(FULL, xn[jj], sl);
                float4 w = Wsh4[(sl * 4 + jj) * 32 + lane];
                acc.x = fmaf(xk, w.x, acc.x);
                acc.y = fmaf(xk, w.y, acc.y);
                acc.z = fmaf(xk, w.z, acc.z);
                acc.w = fmaf(xk, w.w, acc.w);
            }
        }
        ((float4*)(out + ((h * LWIN + l) * tokPerL + t) * 32 + dh))[0] = acc;

        if (which == 0) {
            float sq = acc.x*acc.x + acc.y*acc.y + acc.z*acc.z + acc.w*acc.w;
            sq += __shfl_down_sync(FULL, sq, 4, 8);
            sq += __shfl_down_sync(FULL, sq, 2, 8);
            sq += __shfl_down_sync(FULL, sq, 1, 8);
            if ((lane & 7) == 0)
                SAL[(h * LWIN + l) * tokPerL + t] = sq;
        }
    }
}

// ---------------------------------------------------------------------------
// Kernel 2: keep top-1152 of 1536 saliencies per (h,l).
// ---------------------------------------------------------------------------
__global__ void qkeep_kernel()
{
    __shared__ unsigned keys[QN];
    __shared__ int cnts[2];
    __shared__ int wse[8];
    __shared__ int gtTot;
    const int tid = threadIdx.x, lane = tid & 31, wid = tid >> 5;
    const int row = blockIdx.x;
    const int base = tid * 6;

    for (int i = tid; i < QN; i += 256)
        keys[i] = f2key(SAL[row * QN + i]);
    if (tid < 2) cnts[tid] = 0;
    if (tid == 2) gtTot = 0;
    __syncthreads();

    const unsigned k0 = keys[base+0], k1 = keys[base+1], k2 = keys[base+2],
                   k3 = keys[base+3], k4 = keys[base+4], k5 = keys[base+5];

    unsigned T = 0;
    int exact = 0;
    for (int b = 31; b >= 0; --b) {
        unsigned cand = T | (1u << b);
        unsigned c = (k0>=cand)+(k1>=cand)+(k2>=cand)+(k3>=cand)+(k4>=cand)+(k5>=cand);
        c = __reduce_add_sync(FULL, c);
        if (lane == 0) atomicAdd(&cnts[b & 1], (int)c);
        __syncthreads();
        int tot = cnts[b & 1];
        if (tid == 0) cnts[(b & 1) ^ 1] = 0;
        if (tot >= KEEPQ) { T = cand; if (tot == KEEPQ) exact = 1; }
        __syncthreads();
        if (exact) break;
    }

    unsigned char* Qp = &QKEEP[row * QN + base];
    if (exact) {
        Qp[0] = (k0 >= T); Qp[1] = (k1 >= T); Qp[2] = (k2 >= T);
        Qp[3] = (k3 >= T); Qp[4] = (k4 >= T); Qp[5] = (k5 >= T);
    } else {
        int gtc = (k0>T)+(k1>T)+(k2>T)+(k3>T)+(k4>T)+(k5>T);
        int e0 = (k0==T), e1 = (k1==T), e2 = (k2==T),
            e3 = (k3==T), e4 = (k4==T), e5 = (k5==T);
        int eqc = e0+e1+e2+e3+e4+e5;
        unsigned g = __reduce_add_sync(FULL, (unsigned)gtc);
        if (lane == 0) atomicAdd(&gtTot, (int)g);
        int incl = eqc;
        #pragma unroll
        for (int off = 1; off < 32; off <<= 1) {
            int n = __shfl_up_sync(FULL, incl, off);
            if (lane >= off) incl += n;
        }
        if (lane == 31) wse[wid] = incl;
        __syncthreads();
        int before = 0;
        for (int w = 0; w < wid; ++w) before += wse[w];
        int myExcl = before + incl - eqc;
        int r = (KEEPQ - gtTot) - myExcl;
        int cum = 0;
        Qp[0] = (k0>T) || (e0 && cum < r); cum += e0;
        Qp[1] = (k1>T) || (e1 && cum < r); cum += e1;
        Qp[2] = (k2>T) || (e2 && cum < r); cum += e2;
        Qp[3] = (k3>T) || (e3 && cum < r); cum += e3;
        Qp[4] = (k4>T) || (e4 && cum < r); cum += e4;
        Qp[5] = (k5>T) || (e5 && cum < r);
    }
}

// ---------------------------------------------------------------------------
// Kernel 3: pruned-query result = mean(VH[0:96]) per (h,l).
// ---------------------------------------------------------------------------
__global__ void pmean_kernel()
{
    const int hl = blockIdx.x, d = threadIdx.x;
    float s = 0.f;
    for (int k = 0; k < TOPK; ++k) s += VH[(hl * KN + k) * 32 + d];
    PMEAN[hl * 32 + d] = s * (1.f / (float)TOPK);
}

// ---------------------------------------------------------------------------
// Kernel 4: attention. One block per (h,l). Warp handles 4 queries; 12 k/lane.
// Lockstep top-96 bit-search, counts pair-packed into 16-bit halves:
// 2 REDUX per round for 4 queries. Per-query early exit on count==96.
// ---------------------------------------------------------------------------
__global__ void __launch_bounds__(256, 1) attn_kernel()
{
    extern __shared__ float sm[];
    float* Kt = sm;              // 32 x 388
    float* Vt = sm + 12416;      // 32 x 388
    float* AB = sm + 24832;      // 8 warps * 4 q * 384

    const int hl = blockIdx.x;
    const int tid = threadIdx.x, lane = tid & 31, wid = tid >> 5;

    for (int i = tid; i < KN * 32; i += 256) {
        int k = i >> 5, d = i & 31;
        Kt[d * 388 + k] = KH[hl * (KN * 32) + i];
        Vt[d * 388 + k] = VH[hl * (KN * 32) + i];
    }
    __syncthreads();

    const float pm = PMEAN[hl * 32 + lane];
    float* myAB = AB + wid * 1536;
    const unsigned lt = (1u << lane) - 1u;

    for (int g = wid; g < QN / 4; g += 8) {
        const int q0 = g * 4;
        float qreg[4]; int kp[4];
        #pragma unroll
        for (int qq = 0; qq < 4; ++qq) {
            qreg[qq] = QH[(hl * QN + q0 + qq) * 32 + lane] * SCALE_F;
            kp[qq]   = QKEEP[hl * QN + q0 + qq];
        }

        union { float f[4][12]; unsigned u[4][12]; } A;
        #pragma unroll
        for (int qq = 0; qq < 4; ++qq)
            #pragma unroll
            for (int i = 0; i < 12; ++i) A.f[qq][i] = 0.f;

        // QK^T: lane owns k = lane*12 .. lane*12+11
        #pragma unroll 4
        for (int d = 0; d < 32; ++d) {
            const float4* kr = (const float4*)(Kt + d * 388 + lane * 12);
            float4 c0 = kr[0], c1 = kr[1], c2 = kr[2];
            float kv[12] = {c0.x,c0.y,c0.z,c0.w,c1.x,c1.y,c1.z,c1.w,c2.x,c2.y,c2.z,c2.w};
            #pragma unroll
            for (int qq = 0; qq < 4; ++qq) {
                if (kp[qq]) {                       // warp-uniform
                    float qb = __shfl_sync(FULL, qreg[qq], d);
                    #pragma unroll
                    for (int i = 0; i < 12; ++i)
                        A.f[qq][i] = fmaf(qb, kv[i], A.f[qq][i]);
                }
            }
        }

        // sortable keys in place (kept queries only; others unused)
        #pragma unroll
        for (int qq = 0; qq < 4; ++qq)
            if (kp[qq]) {
                #pragma unroll
                for (int i = 0; i < 12; ++i)
                    A.u[qq][i] = f2key(A.f[qq][i]);
            }

        // batched bitwise threshold search; counts packed 2-per-reduce
        unsigned T[4] = {0u, 0u, 0u, 0u};
        int act = (kp[0] ? 1 : 0) | (kp[1] ? 2 : 0) | (kp[2] ? 4 : 0) | (kp[3] ? 8 : 0);
        int exact = 0;
        for (int b = 31; b >= 0; --b) {
            int still = act & ~exact;
            if (!still) break;
            const unsigned bit = 1u << b;
            unsigned cand0 = T[0] | bit, cand1 = T[1] | bit,
                     cand2 = T[2] | bit, cand3 = T[3] | bit;
            unsigned p01 = 0, p23 = 0;
            #pragma unroll
            for (int i = 0; i < 12; ++i) {
                p01 += (A.u[0][i] >= cand0 ? 1u : 0u) | (A.u[1][i] >= cand1 ? 0x10000u : 0u);
                p23 += (A.u[2][i] >= cand2 ? 1u : 0u) | (A.u[3][i] >= cand3 ? 0x10000u : 0u);
            }
            p01 = __reduce_add_sync(FULL, p01);
            p23 = __reduce_add_sync(FULL, p23);
            unsigned c[4] = { p01 & 0xFFFFu, p01 >> 16, p23 & 0xFFFFu, p23 >> 16 };
            #pragma unroll
            for (int qq = 0; qq < 4; ++qq) {
                if (((still >> qq) & 1) && c[qq] >= (unsigned)TOPK) {
                    T[qq] |= bit;
                    if (c[qq] == (unsigned)TOPK) exact |= 1 << qq;
                }
            }
        }

        // keep mask + softmax per kept query
        #pragma unroll
        for (int qq = 0; qq < 4; ++qq) {
            if (!kp[qq]) continue;                  // warp-uniform
            bool keep[12];
            if ((exact >> qq) & 1) {
                #pragma unroll
                for (int i = 0; i < 12; ++i) keep[i] = (A.u[qq][i] >= T[qq]);
            } else {
                unsigned Tq = T[qq];
                unsigned cg = 0;
                #pragma unroll
                for (int i = 0; i < 12; ++i) cg += (A.u[qq][i] > Tq) ? 1u : 0u;
                cg = __reduce_add_sync(FULL, cg);
                int rem = (int)TOPK - (int)cg;
                int pre = 0;
                #pragma unroll
                for (int i = 0; i < 12; ++i) {
                    unsigned m = __ballot_sync(FULL, A.u[qq][i] == Tq);
                    pre += __popc(m & lt);
                }
                int cum = 0;
                #pragma unroll
                for (int i = 0; i < 12; ++i) {
                    bool eq = (A.u[qq][i] == Tq);
                    keep[i] = (A.u[qq][i] > Tq) || (eq && (pre + cum) < rem);
                    cum += eq ? 1 : 0;
                }
            }
            unsigned km = A.u[qq][0];
            #pragma unroll
            for (int i = 1; i < 12; ++i) km = max(km, A.u[qq][i]);
            #pragma unroll
            for (int off = 16; off > 0; off >>= 1)
                km = max(km, __shfl_xor_sync(FULL, km, off));
            float mx = key2f(km);

            float e[12]; float ssum = 0.f;
            #pragma unroll
            for (int i = 0; i < 12; ++i) {
                float ev = keep[i] ? __expf(key2f(A.u[qq][i]) - mx) : 0.f;
                e[i] = ev; ssum += ev;
            }
            #pragma unroll
            for (int off = 16; off > 0; off >>= 1)
                ssum += __shfl_xor_sync(FULL, ssum, off);
            float inv = 1.f / ssum;
            float4* dst = (float4*)(myAB + qq * 384 + lane * 12);
            dst[0] = make_float4(e[0]*inv, e[1]*inv, e[2]*inv,  e[3]*inv);
            dst[1] = make_float4(e[4]*inv, e[5]*inv, e[6]*inv,  e[7]*inv);
            dst[2] = make_float4(e[8]*inv, e[9]*inv, e[10]*inv, e[11]*inv);
        }
        __syncwarp();

        // AV: lane = output dim; V load amortized across 4 queries
        float o0 = 0.f, o1 = 0.f, o2 = 0.f, o3 = 0.f;
        const float4* vr  = (const float4*)(Vt + lane * 388);
        const float4* a0p = (const float4*)(myAB);
        const float4* a1p = (const float4*)(myAB + 384);
        const float4* a2p = (const float4*)(myAB + 768);
        const float4* a3p = (const float4*)(myAB + 1152);
        #pragma unroll 4
        for (int c = 0; c < KN / 4; ++c) {
            float4 v4 = vr[c];
            float4 a;
            if (kp[0]) { a = a0p[c]; o0 += a.x*v4.x + a.y*v4.y + a.z*v4.z + a.w*v4.w; }
            if (kp[1]) { a = a1p[c]; o1 += a.x*v4.x + a.y*v4.y + a.z*v4.z + a.w*v4.w; }
            if (kp[2]) { a = a2p[c]; o2 += a.x*v4.x + a.y*v4.y + a.z*v4.z + a.w*v4.w; }
            if (kp[3]) { a = a3p[c]; o3 += a.x*v4.x + a.y*v4.y + a.z*v4.z + a.w*v4.w; }
        }
        __syncwarp();

        float outs[4] = {o0, o1, o2, o3};
        #pragma unroll
        for (int qq = 0; qq < 4; ++qq)
            AO[(hl * QN + q0 + qq) * 32 + lane] = kp[qq] ? outs[qq] : pm;
    }
}

// ---------------------------------------------------------------------------
// Kernel 5: camera-mean -> output projection -> + bp + skip. Warp per token.
// ---------------------------------------------------------------------------
__global__ void final_kernel(const float* __restrict__ skip,
                             const float* __restrict__ Wp,
                             const float* __restrict__ bp,
                             float* __restrict__ outp)
{
    extern __shared__ float Wsh[];
    for (int i = threadIdx.x; i < 128 * 128 / 4; i += blockDim.x)
        ((float4*)Wsh)[i] = ((const float4*)Wp)[i];
    __syncthreads();

    const int lane = threadIdx.x & 31;
    const int wid  = threadIdx.x >> 5;
    const int nwarps = (blockDim.x >> 5) * gridDim.x;
    int gw = blockIdx.x * (blockDim.x >> 5) + wid;
    const float4* Wsh4 = (const float4*)Wsh;
    const float4 bi = ((const float4*)bp)[lane];
    const int h = lane >> 3, dbase = (lane & 7) * 4;

    for (int o = gw; o < LWIN * 256; o += nwarps) {
        int l = o >> 8, rr = o & 255;
        float4 ab = make_float4(0.f,0.f,0.f,0.f);
        #pragma unroll
        for (int n = 0; n < NCAM; ++n) {
            float4 t = ((const float4*)(AO + ((h * LWIN + l) * QN + n * 256 + rr) * 32 + dbase))[0];
            ab.x += t.x; ab.y += t.y; ab.z += t.z; ab.w += t.w;
        }
        const float inv6 = 1.f / 6.f;
        float xn[4] = {ab.x*inv6, ab.y*inv6, ab.z*inv6, ab.w*inv6};

        float4 acc = bi;
        #pragma unroll 8
        for (int sl = 0; sl < 32; ++sl) {
            #pragma unroll
            for (int jj = 0; jj < 4; ++jj) {
                float xk = __shfl_sync(FULL, xn[jj], sl);
                float4 w = Wsh4[(sl * 4 + jj) * 32 + lane];
                acc.x = fmaf(xk, w.x, acc.x);
                acc.y = fmaf(xk, w.y, acc.y);
                acc.z = fmaf(xk, w.z, acc.z);
                acc.w = fmaf(xk, w.w, acc.w);
            }
        }
        float4 sk = ((const float4*)(skip + o * DIMF))[lane];
        acc.x += sk.x; acc.y += sk.y; acc.z += sk.z; acc.w += sk.w;
        ((float4*)(outp + o * DIMF))[lane] = acc;
    }
}

// ---------------------------------------------------------------------------
// Inputs: 0 q, 1 k, 2 v, 3 skip, 4 logit_bias (dead), 5 g_q, 6 b_q, 7 g_k,
// 8 b_k, 9 g_v, 10 b_v, 11 Wq, 12 bq, 13 Wk, 14 bk, 15 Wv, 16 bv, 17 Wp, 18 bp
// ---------------------------------------------------------------------------
extern "C" void kernel_launch(void* const* d_in, const int* in_sizes, int n_in,
                              void* d_out, int out_size)
{
    const float* q    = (const float*)d_in[0];
    const float* k    = (const float*)d_in[1];
    const float* v    = (const float*)d_in[2];
    const float* skip = (const float*)d_in[3];
    const float* g_q  = (const float*)d_in[5];
    const float* b_q  = (const float*)d_in[6];
    const float* g_k  = (const float*)d_in[7];
    const float* b_k  = (const float*)d_in[8];
    const float* g_v  = (const float*)d_in[9];
    const float* b_v  = (const float*)d_in[10];
    const float* Wq   = (const float*)d_in[11];
    const float* bq   = (const float*)d_in[12];
    const float* Wk   = (const float*)d_in[13];
    const float* bk   = (const float*)d_in[14];
    const float* Wv   = (const float*)d_in[15];
    const float* bv   = (const float*)d_in[16];
    const float* Wp   = (const float*)d_in[17];
    const float* bp   = (const float*)d_in[18];
    float* outp = (float*)d_out;

    cudaFuncSetAttribute(proj_kernel,  cudaFuncAttributeMaxDynamicSharedMemorySize, 65536);
    cudaFuncSetAttribute(attn_kernel,  cudaFuncAttributeMaxDynamicSharedMemorySize, 148480);
    cudaFuncSetAttribute(final_kernel, cudaFuncAttributeMaxDynamicSharedMemorySize, 65536);

    proj_kernel<<<148, 256, 65536>>>(q, g_q, b_q, Wq, bq, QN, 16, 0);
    proj_kernel<<<148, 256, 65536>>>(k, g_k, b_k, Wk, bk, KN, 8, 1);
    proj_kernel<<<148, 256, 65536>>>(v, g_v, b_v, Wv, bv, KN, 8, 2);
    qkeep_kernel<<<HL, 256>>>();
    pmean_kernel<<<HL, 32>>>();
    attn_kernel<<<HL, 256, 148480>>>();
    final_kernel<<<148, 256, 65536>>>(skip, Wp, bp, outp);
}

// round 13
// speedup vs baseline: 1.7592x; 1.2808x over previous
#include <cuda_runtime.h>

#define FULL 0xFFFFFFFFu
#define NCAM 6
#define LWIN 36
#define QN   1536
#define KN   384
#define HL   144
#define DIMF 128
#define KEEPQ 1152
#define TOPK  96
#define SCALE_F 0.17677669529663687f

#define QBLK 296
#define KBLK 74
#define VBLK 74

__device__ float QH[HL * QN * 32];
__device__ float KH[HL * KN * 32];
__device__ float VH[HL * KN * 32];
__device__ float AO[HL * QN * 32];
__device__ float SAL[HL * QN];
__device__ unsigned char QKEEP[HL * QN];
__device__ float PMEAN[HL * 32];

__device__ __forceinline__ unsigned f2key(float f) {
    unsigned u = __float_as_uint(f);
    return (u & 0x80000000u) ? ~u : (u | 0x80000000u);
}
__device__ __forceinline__ float key2f(unsigned k) {
    return __uint_as_float((k & 0x80000000u) ? (k ^ 0x80000000u) : ~k);
}

// ---------------------------------------------------------------------------
// Kernel 1: merged q/k/v projection. Segmented grid so all three run
// concurrently (single launch): [0,QBLK) -> q, [QBLK,QBLK+KBLK) -> k, rest v.
// Warp per token: window rearrange + LayerNorm + 128x128 GEMM (+SAL for q).
// ---------------------------------------------------------------------------
__global__ void proj_all_kernel(
    const float* __restrict__ in_q, const float* __restrict__ in_k,
    const float* __restrict__ in_v,
    const float* __restrict__ g_q, const float* __restrict__ b_q,
    const float* __restrict__ g_k, const float* __restrict__ b_k,
    const float* __restrict__ g_v, const float* __restrict__ b_v,
    const float* __restrict__ Wq, const float* __restrict__ bq,
    const float* __restrict__ Wk, const float* __restrict__ bk,
    const float* __restrict__ Wv, const float* __restrict__ bv)
{
    extern __shared__ float Wsh[];

    int blk = blockIdx.x;
    int which, lb, segBlocks, tokPerL, wsz;
    const float *in, *gamma, *beta, *W, *bias;
    float* out;
    if (blk < QBLK) {
        which = 0; lb = blk; segBlocks = QBLK; tokPerL = QN; wsz = 16;
        in = in_q; gamma = g_q; beta = b_q; W = Wq; bias = bq; out = QH;
    } else if (blk < QBLK + KBLK) {
        which = 1; lb = blk - QBLK; segBlocks = KBLK; tokPerL = KN; wsz = 8;
        in = in_k; gamma = g_k; beta = b_k; W = Wk; bias = bk; out = KH;
    } else {
        which = 2; lb = blk - QBLK - KBLK; segBlocks = VBLK; tokPerL = KN; wsz = 8;
        in = in_v; gamma = g_v; beta = b_v; W = Wv; bias = bv; out = VH;
    }

    for (int i = threadIdx.x; i < 128 * 128 / 4; i += blockDim.x)
        ((float4*)Wsh)[i] = ((const float4*)W)[i];
    __syncthreads();

    const int lane = threadIdx.x & 31;
    const int wid  = threadIdx.x >> 5;
    const int nwarps = (blockDim.x >> 5) * segBlocks;
    int gw = lb * (blockDim.x >> 5) + wid;
    const float4* Wsh4 = (const float4*)Wsh;

    const float4 gm = ((const float4*)gamma)[lane];
    const float4 bt = ((const float4*)beta)[lane];
    const float4 bi = ((const float4*)bias)[lane];
    const int ww = wsz * wsz;
    const int h = lane >> 3, dh = (lane & 7) * 4;
    const int nTok = LWIN * tokPerL;

    for (int o = gw; o < nTok; o += nwarps) {
        int l = o / tokPerL, t = o - l * tokPerL;
        int n = t / ww, r = t - n * ww;
        int w1 = r / wsz, w2 = r - w1 * wsz;
        int x = l / 6, y = l - x * 6;
        int inIdx = ((((n * 6 + x) * 6 + y) * wsz + w1) * wsz + w2) * DIMF;

        float4 xv = ((const float4*)(in + inIdx))[lane];
        float s  = xv.x + xv.y + xv.z + xv.w;
        float ss = xv.x*xv.x + xv.y*xv.y + xv.z*xv.z + xv.w*xv.w;
        #pragma unroll
        for (int off = 16; off > 0; off >>= 1) {
            s  += __shfl_xor_sync(FULL, s,  off);
            ss += __shfl_xor_sync(FULL, ss, off);
        }
        float mu   = s * (1.f / 128.f);
        float var  = ss * (1.f / 128.f) - mu * mu;
        float rstd = rsqrtf(var + 1e-5f);

        float xn[4];
        xn[0] = (xv.x - mu) * rstd * gm.x + bt.x;
        xn[1] = (xv.y - mu) * rstd * gm.y + bt.y;
        xn[2] = (xv.z - mu) * rstd * gm.z + bt.z;
        xn[3] = (xv.w - mu) * rstd * gm.w + bt.w;

        float4 acc = bi;
        #pragma unroll 8
        for (int sl = 0; sl < 32; ++sl) {
            #pragma unroll
            for (int jj = 0; jj < 4; ++jj) {
                float xk = __shfl_sync(FULL, xn[jj], sl);
                float4 w = Wsh4[(sl * 4 + jj) * 32 + lane];
                acc.x = fmaf(xk, w.x, acc.x);
                acc.y = fmaf(xk, w.y, acc.y);
                acc.z = fmaf(xk, w.z, acc.z);
                acc.w = fmaf(xk, w.w, acc.w);
            }
        }
        ((float4*)(out + ((h * LWIN + l) * tokPerL + t) * 32 + dh))[0] = acc;

        if (which == 0) {
            float sq = acc.x*acc.x + acc.y*acc.y + acc.z*acc.z + acc.w*acc.w;
            sq += __shfl_down_sync(FULL, sq, 4, 8);
            sq += __shfl_down_sync(FULL, sq, 2, 8);
            sq += __shfl_down_sync(FULL, sq, 1, 8);
            if ((lane & 7) == 0)
                SAL[(h * LWIN + l) * tokPerL + t] = sq;
        }
    }
}

// ---------------------------------------------------------------------------
// Kernel 2: keep top-1152 of 1536 saliencies per (h,l).
// ---------------------------------------------------------------------------
__global__ void qkeep_kernel()
{
    __shared__ unsigned keys[QN];
    __shared__ int cnts[2];
    __shared__ int wse[8];
    __shared__ int gtTot;
    const int tid = threadIdx.x, lane = tid & 31, wid = tid >> 5;
    const int row = blockIdx.x;
    const int base = tid * 6;

    for (int i = tid; i < QN; i += 256)
        keys[i] = f2key(SAL[row * QN + i]);
    if (tid < 2) cnts[tid] = 0;
    if (tid == 2) gtTot = 0;
    __syncthreads();

    const unsigned k0 = keys[base+0], k1 = keys[base+1], k2 = keys[base+2],
                   k3 = keys[base+3], k4 = keys[base+4], k5 = keys[base+5];

    unsigned T = 0;
    int exact = 0;
    for (int b = 31; b >= 0; --b) {
        unsigned cand = T | (1u << b);
        unsigned c = (k0>=cand)+(k1>=cand)+(k2>=cand)+(k3>=cand)+(k4>=cand)+(k5>=cand);
        c = __reduce_add_sync(FULL, c);
        if (lane == 0) atomicAdd(&cnts[b & 1], (int)c);
        __syncthreads();
        int tot = cnts[b & 1];
        if (tid == 0) cnts[(b & 1) ^ 1] = 0;
        if (tot >= KEEPQ) { T = cand; if (tot == KEEPQ) exact = 1; }
        __syncthreads();
        if (exact) break;
    }

    unsigned char* Qp = &QKEEP[row * QN + base];
    if (exact) {
        Qp[0] = (k0 >= T); Qp[1] = (k1 >= T); Qp[2] = (k2 >= T);
        Qp[3] = (k3 >= T); Qp[4] = (k4 >= T); Qp[5] = (k5 >= T);
    } else {
        int gtc = (k0>T)+(k1>T)+(k2>T)+(k3>T)+(k4>T)+(k5>T);
        int e0 = (k0==T), e1 = (k1==T), e2 = (k2==T),
            e3 = (k3==T), e4 = (k4==T), e5 = (k5==T);
        int eqc = e0+e1+e2+e3+e4+e5;
        unsigned g = __reduce_add_sync(FULL, (unsigned)gtc);
        if (lane == 0) atomicAdd(&gtTot, (int)g);
        int incl = eqc;
        #pragma unroll
        for (int off = 1; off < 32; off <<= 1) {
            int n = __shfl_up_sync(FULL, incl, off);
            if (lane >= off) incl += n;
        }
        if (lane == 31) wse[wid] = incl;
        __syncthreads();
        int before = 0;
        for (int w = 0; w < wid; ++w) before += wse[w];
        int myExcl = before + incl - eqc;
        int r = (KEEPQ - gtTot) - myExcl;
        int cum = 0;
        Qp[0] = (k0>T) || (e0 && cum < r); cum += e0;
        Qp[1] = (k1>T) || (e1 && cum < r); cum += e1;
        Qp[2] = (k2>T) || (e2 && cum < r); cum += e2;
        Qp[3] = (k3>T) || (e3 && cum < r); cum += e3;
        Qp[4] = (k4>T) || (e4 && cum < r); cum += e4;
        Qp[5] = (k5>T) || (e5 && cum < r);
    }
}

// ---------------------------------------------------------------------------
// Kernel 3: pruned-query result = mean(VH[0:96]) per (h,l).
// ---------------------------------------------------------------------------
__global__ void pmean_kernel()
{
    const int hl = blockIdx.x, d = threadIdx.x;
    float s = 0.f;
    for (int k = 0; k < TOPK; ++k) s += VH[(hl * KN + k) * 32 + d];
    PMEAN[hl * 32 + d] = s * (1.f / (float)TOPK);
}

// ---------------------------------------------------------------------------
// Kernel 4: attention. One block per (h,l), 512 threads (16 warps = 4/SMSP).
// Warp handles 4 queries; 12 k/lane. Lockstep top-96 bit-search with
// pair-packed counts (2 REDUX/round for 4 queries), early exit on count==96.
// smem: Kt 32x388 + Vt 32x388 + AB 16*4*384 = 197632 B (1 block/SM).
// ---------------------------------------------------------------------------
__global__ void __launch_bounds__(512, 1) attn_kernel()
{
    extern __shared__ float sm[];
    float* Kt = sm;              // 32 x 388
    float* Vt = sm + 12416;      // 32 x 388
    float* AB = sm + 24832;      // 16 warps * 4 q * 384

    const int hl = blockIdx.x;
    const int tid = threadIdx.x, lane = tid & 31, wid = tid >> 5;

    for (int i = tid; i < KN * 32; i += 512) {
        int k = i >> 5, d = i & 31;
        Kt[d * 388 + k] = KH[hl * (KN * 32) + i];
        Vt[d * 388 + k] = VH[hl * (KN * 32) + i];
    }
    __syncthreads();

    const float pm = PMEAN[hl * 32 + lane];
    float* myAB = AB + wid * 1536;
    const unsigned lt = (1u << lane) - 1u;

    for (int g = wid; g < QN / 4; g += 16) {
        const int q0 = g * 4;
        float qreg[4]; int kp[4];
        #pragma unroll
        for (int qq = 0; qq < 4; ++qq) {
            qreg[qq] = QH[(hl * QN + q0 + qq) * 32 + lane] * SCALE_F;
            kp[qq]   = QKEEP[hl * QN + q0 + qq];
        }

        union { float f[4][12]; unsigned u[4][12]; } A;
        #pragma unroll
        for (int qq = 0; qq < 4; ++qq)
            #pragma unroll
            for (int i = 0; i < 12; ++i) A.f[qq][i] = 0.f;

        // QK^T: lane owns k = lane*12 .. lane*12+11
        #pragma unroll 4
        for (int d = 0; d < 32; ++d) {
            const float4* kr = (const float4*)(Kt + d * 388 + lane * 12);
            float4 c0 = kr[0], c1 = kr[1], c2 = kr[2];
            float kv[12] = {c0.x,c0.y,c0.z,c0.w,c1.x,c1.y,c1.z,c1.w,c2.x,c2.y,c2.z,c2.w};
            #pragma unroll
            for (int qq = 0; qq < 4; ++qq) {
                if (kp[qq]) {                       // warp-uniform
                    float qb = __shfl_sync(FULL, qreg[qq], d);
                    #pragma unroll
                    for (int i = 0; i < 12; ++i)
                        A.f[qq][i] = fmaf(qb, kv[i], A.f[qq][i]);
                }
            }
        }

        // sortable keys in place (kept queries only)
        #pragma unroll
        for (int qq = 0; qq < 4; ++qq)
            if (kp[qq]) {
                #pragma unroll
                for (int i = 0; i < 12; ++i)
                    A.u[qq][i] = f2key(A.f[qq][i]);
            }

        // batched bitwise threshold search; counts packed 2-per-reduce
        unsigned T[4] = {0u, 0u, 0u, 0u};
        int act = (kp[0] ? 1 : 0) | (kp[1] ? 2 : 0) | (kp[2] ? 4 : 0) | (kp[3] ? 8 : 0);
        int exact = 0;
        for (int b = 31; b >= 0; --b) {
            int still = act & ~exact;
            if (!still) break;
            const unsigned bit = 1u << b;
            unsigned cand0 = T[0] | bit, cand1 = T[1] | bit,
                     cand2 = T[2] | bit, cand3 = T[3] | bit;
            unsigned p01 = 0, p23 = 0;
            #pragma unroll
            for (int i = 0; i < 12; ++i) {
                p01 += (A.u[0][i] >= cand0 ? 1u : 0u) | (A.u[1][i] >= cand1 ? 0x10000u : 0u);
                p23 += (A.u[2][i] >= cand2 ? 1u : 0u) | (A.u[3][i] >= cand3 ? 0x10000u : 0u);
            }
            p01 = __reduce_add_sync(FULL, p01);
            p23 = __reduce_add_sync(FULL, p23);
            unsigned c[4] = { p01 & 0xFFFFu, p01 >> 16, p23 & 0xFFFFu, p23 >> 16 };
            #pragma unroll
            for (int qq = 0; qq < 4; ++qq) {
                if (((still >> qq) & 1) && c[qq] >= (unsigned)TOPK) {
                    T[qq] |= bit;
                    if (c[qq] == (unsigned)TOPK) exact |= 1 << qq;
                }
            }
        }

        // keep mask + softmax per kept query
        #pragma unroll
        for (int qq = 0; qq < 4; ++qq) {
            if (!kp[qq]) continue;                  // warp-uniform
            bool keep[12];
            if ((exact >> qq) & 1) {
                #pragma unroll
                for (int i = 0; i < 12; ++i) keep[i] = (A.u[qq][i] >= T[qq]);
            } else {
                unsigned Tq = T[qq];
                unsigned cg = 0;
                #pragma unroll
                for (int i = 0; i < 12; ++i) cg += (A.u[qq][i] > Tq) ? 1u : 0u;
                cg = __reduce_add_sync(FULL, cg);
                int rem = (int)TOPK - (int)cg;
                int pre = 0;
                #pragma unroll
                for (int i = 0; i < 12; ++i) {
                    unsigned m = __ballot_sync(FULL, A.u[qq][i] == Tq);
                    pre += __popc(m & lt);
                }
                int cum = 0;
                #pragma unroll
                for (int i = 0; i < 12; ++i) {
                    bool eq = (A.u[qq][i] == Tq);
                    keep[i] = (A.u[qq][i] > Tq) || (eq && (pre + cum) < rem);
                    cum += eq ? 1 : 0;
                }
            }
            unsigned km = A.u[qq][0];
            #pragma unroll
            for (int i = 1; i < 12; ++i) km = max(km, A.u[qq][i]);
            #pragma unroll
            for (int off = 16; off > 0; off >>= 1)
                km = max(km, __shfl_xor_sync(FULL, km, off));
            float mx = key2f(km);

            float e[12]; float ssum = 0.f;
            #pragma unroll
            for (int i = 0; i < 12; ++i) {
                float ev = keep[i] ? __expf(key2f(A.u[qq][i]) - mx) : 0.f;
                e[i] = ev; ssum += ev;
            }
            #pragma unroll
            for (int off = 16; off > 0; off >>= 1)
                ssum += __shfl_xor_sync(FULL, ssum, off);
            float inv = 1.f / ssum;
            float4* dst = (float4*)(myAB + qq * 384 + lane * 12);
            dst[0] = make_float4(e[0]*inv, e[1]*inv, e[2]*inv,  e[3]*inv);
            dst[1] = make_float4(e[4]*inv, e[5]*inv, e[6]*inv,  e[7]*inv);
            dst[2] = make_float4(e[8]*inv, e[9]*inv, e[10]*inv, e[11]*inv);
        }
        __syncwarp();

        // AV: lane = output dim; V load amortized across 4 queries
        float o0 = 0.f, o1 = 0.f, o2 = 0.f, o3 = 0.f;
        const float4* vr  = (const float4*)(Vt + lane * 388);
        const float4* a0p = (const float4*)(myAB);
        const float4* a1p = (const float4*)(myAB + 384);
        const float4* a2p = (const float4*)(myAB + 768);
        const float4* a3p = (const float4*)(myAB + 1152);
        #pragma unroll 4
        for (int c = 0; c < KN / 4; ++c) {
            float4 v4 = vr[c];
            float4 a;
            if (kp[0]) { a = a0p[c]; o0 += a.x*v4.x + a.y*v4.y + a.z*v4.z + a.w*v4.w; }
            if (kp[1]) { a = a1p[c]; o1 += a.x*v4.x + a.y*v4.y + a.z*v4.z + a.w*v4.w; }
            if (kp[2]) { a = a2p[c]; o2 += a.x*v4.x + a.y*v4.y + a.z*v4.z + a.w*v4.w; }
            if (kp[3]) { a = a3p[c]; o3 += a.x*v4.x + a.y*v4.y + a.z*v4.z + a.w*v4.w; }
        }
        __syncwarp();

        float outs[4] = {o0, o1, o2, o3};
        #pragma unroll
        for (int qq = 0; qq < 4; ++qq)
            AO[(hl * QN + q0 + qq) * 32 + lane] = kp[qq] ? outs[qq] : pm;
    }
}

// ---------------------------------------------------------------------------
// Kernel 5: camera-mean -> output projection -> + bp + skip. Warp per token.
// ---------------------------------------------------------------------------
__global__ void final_kernel(const float* __restrict__ skip,
                             const float* __restrict__ Wp,
                             const float* __restrict__ bp,
                             float* __restrict__ outp)
{
    extern __shared__ float Wsh[];
    for (int i = threadIdx.x; i < 128 * 128 / 4; i += blockDim.x)
        ((float4*)Wsh)[i] = ((const float4*)Wp)[i];
    __syncthreads();

    const int lane = threadIdx.x & 31;
    const int wid  = threadIdx.x >> 5;
    const int nwarps = (blockDim.x >> 5) * gridDim.x;
    int gw = blockIdx.x * (blockDim.x >> 5) + wid;
    const float4* Wsh4 = (const float4*)Wsh;
    const float4 bi = ((const float4*)bp)[lane];
    const int h = lane >> 3, dbase = (lane & 7) * 4;

    for (int o = gw; o < LWIN * 256; o += nwarps) {
        int l = o >> 8, rr = o & 255;
        float4 ab = make_float4(0.f,0.f,0.f,0.f);
        #pragma unroll
        for (int n = 0; n < NCAM; ++n) {
            float4 t = ((const float4*)(AO + ((h * LWIN + l) * QN + n * 256 + rr) * 32 + dbase))[0];
            ab.x += t.x; ab.y += t.y; ab.z += t.z; ab.w += t.w;
        }
        const float inv6 = 1.f / 6.f;
        float xn[4] = {ab.x*inv6, ab.y*inv6, ab.z*inv6, ab.w*inv6};

        float4 acc = bi;
        #pragma unroll 8
        for (int sl = 0; sl < 32; ++sl) {
            #pragma unroll
            for (int jj = 0; jj < 4; ++jj) {
                float xk = __shfl_sync(FULL, xn[jj], sl);
                float4 w = Wsh4[(sl * 4 + jj) * 32 + lane];
                acc.x = fmaf(xk, w.x, acc.x);
                acc.y = fmaf(xk, w.y, acc.y);
                acc.z = fmaf(xk, w.z, acc.z);
                acc.w = fmaf(xk, w.w, acc.w);
            }
        }
        float4 sk = ((const float4*)(skip + o * DIMF))[lane];
        acc.x += sk.x; acc.y += sk.y; acc.z += sk.z; acc.w += sk.w;
        ((float4*)(outp + o * DIMF))[lane] = acc;
    }
}

// ---------------------------------------------------------------------------
// Inputs: 0 q, 1 k, 2 v, 3 skip, 4 logit_bias (dead), 5 g_q, 6 b_q, 7 g_k,
// 8 b_k, 9 g_v, 10 b_v, 11 Wq, 12 bq, 13 Wk, 14 bk, 15 Wv, 16 bv, 17 Wp, 18 bp
// ---------------------------------------------------------------------------
extern "C" void kernel_launch(void* const* d_in, const int* in_sizes, int n_in,
                              void* d_out, int out_size)
{
    const float* q    = (const float*)d_in[0];
    const float* k    = (const float*)d_in[1];
    const float* v    = (const float*)d_in[2];
    const float* skip = (const float*)d_in[3];
    const float* g_q  = (const float*)d_in[5];
    const float* b_q  = (const float*)d_in[6];
    const float* g_k  = (const float*)d_in[7];
    const float* b_k  = (const float*)d_in[8];
    const float* g_v  = (const float*)d_in[9];
    const float* b_v  = (const float*)d_in[10];
    const float* Wq   = (const float*)d_in[11];
    const float* bq   = (const float*)d_in[12];
    const float* Wk   = (const float*)d_in[13];
    const float* bk   = (const float*)d_in[14];
    const float* Wv   = (const float*)d_in[15];
    const float* bv   = (const float*)d_in[16];
    const float* Wp   = (const float*)d_in[17];
    const float* bp   = (const float*)d_in[18];
    float* outp = (float*)d_out;

    cudaFuncSetAttribute(proj_all_kernel, cudaFuncAttributeMaxDynamicSharedMemorySize, 65536);
    cudaFuncSetAttribute(attn_kernel,     cudaFuncAttributeMaxDynamicSharedMemorySize, 197632);
    cudaFuncSetAttribute(final_kernel,    cudaFuncAttributeMaxDynamicSharedMemorySize, 65536);

    proj_all_kernel<<<QBLK + KBLK + VBLK, 256, 65536>>>(
        q, k, v, g_q, b_q, g_k, b_k, g_v, b_v,
        Wq, bq, Wk, bk, Wv, bv);
    qkeep_kernel<<<HL, 256>>>();
    pmean_kernel<<<HL, 32>>>();
    attn_kernel<<<HL, 512, 197632>>>();
    final_kernel<<<148, 256, 65536>>>(skip, Wp, bp, outp);
}

// round 14
// speedup vs baseline: 1.8126x; 1.0304x over previous
#include <cuda_runtime.h>

#define FULL 0xFFFFFFFFu
#define NCAM 6
#define LWIN 36
#define QN   1536
#define KN   384
#define HL   144
#define DIMF 128
#define KEEPQ 1152
#define TOPK  96
#define SCALE_F 0.17677669529663687f

#define QBLK 296
#define KBLK 74
#define VBLK 74

__device__ float QH[HL * QN * 32];
__device__ float KH[HL * KN * 32];
__device__ float VH[HL * KN * 32];
__device__ float AO[HL * QN * 32];
__device__ float SAL[HL * QN];
__device__ unsigned char QKEEP[HL * QN];
__device__ float PMEAN[HL * 32];

typedef unsigned long long u64t;

__device__ __forceinline__ unsigned f2key(float f) {
    unsigned u = __float_as_uint(f);
    return (u & 0x80000000u) ? ~u : (u | 0x80000000u);
}
__device__ __forceinline__ unsigned bits2key(unsigned u) {
    return (u & 0x80000000u) ? ~u : (u | 0x80000000u);
}
__device__ __forceinline__ float key2f(unsigned k) {
    return __uint_as_float((k & 0x80000000u) ? (k ^ 0x80000000u) : ~k);
}
__device__ __forceinline__ u64t pack2(float lo, float hi) {
    u64t r;
    asm("mov.b64 %0, {%1, %2};" : "=l"(r) : "f"(lo), "f"(hi));
    return r;
}
__device__ __forceinline__ void unpack2(u64t p, float& lo, float& hi) {
    asm("mov.b64 {%0, %1}, %2;" : "=f"(lo), "=f"(hi) : "l"(p));
}
__device__ __forceinline__ u64t fma2(u64t a, u64t b, u64t c) {
    u64t d;
    asm("fma.rn.f32x2 %0, %1, %2, %3;" : "=l"(d) : "l"(a), "l"(b), "l"(c));
    return d;
}

// ---------------------------------------------------------------------------
// Kernel 1: merged q/k/v projection (segmented grid). Warp per token:
// window rearrange + LayerNorm + 128x128 GEMM via packed f32x2 FMA (+SAL q).
// ---------------------------------------------------------------------------
__global__ void proj_all_kernel(
    const float* __restrict__ in_q, const float* __restrict__ in_k,
    const float* __restrict__ in_v,
    const float* __restrict__ g_q, const float* __restrict__ b_q,
    const float* __restrict__ g_k, const float* __restrict__ b_k,
    const float* __restrict__ g_v, const float* __restrict__ b_v,
    const float* __restrict__ Wq, const float* __restrict__ bq,
    const float* __restrict__ Wk, const float* __restrict__ bk,
    const float* __restrict__ Wv, const float* __restrict__ bv)
{
    extern __shared__ float Wsh[];

    int blk = blockIdx.x;
    int which, lb, segBlocks, tokPerL, wsz;
    const float *in, *gamma, *beta, *W, *bias;
    float* out;
    if (blk < QBLK) {
        which = 0; lb = blk; segBlocks = QBLK; tokPerL = QN; wsz = 16;
        in = in_q; gamma = g_q; beta = b_q; W = Wq; bias = bq; out = QH;
    } else if (blk < QBLK + KBLK) {
        which = 1; lb = blk - QBLK; segBlocks = KBLK; tokPerL = KN; wsz = 8;
        in = in_k; gamma = g_k; beta = b_k; W = Wk; bias = bk; out = KH;
    } else {
        which = 2; lb = blk - QBLK - KBLK; segBlocks = VBLK; tokPerL = KN; wsz = 8;
        in = in_v; gamma = g_v; beta = b_v; W = Wv; bias = bv; out = VH;
    }

    for (int i = threadIdx.x; i < 128 * 128 / 4; i += blockDim.x)
        ((float4*)Wsh)[i] = ((const float4*)W)[i];
    __syncthreads();

    const int lane = threadIdx.x & 31;
    const int wid  = threadIdx.x >> 5;
    const int nwarps = (blockDim.x >> 5) * segBlocks;
    int gw = lb * (blockDim.x >> 5) + wid;
    const ulonglong2* Wsh2 = (const ulonglong2*)Wsh;

    const float4 gm = ((const float4*)gamma)[lane];
    const float4 bt = ((const float4*)beta)[lane];
    const float4 bi = ((const float4*)bias)[lane];
    const int ww = wsz * wsz;
    const int h = lane >> 3, dh = (lane & 7) * 4;
    const int nTok = LWIN * tokPerL;

    for (int o = gw; o < nTok; o += nwarps) {
        int l = o / tokPerL, t = o - l * tokPerL;
        int n = t / ww, r = t - n * ww;
        int w1 = r / wsz, w2 = r - w1 * wsz;
        int x = l / 6, y = l - x * 6;
        int inIdx = ((((n * 6 + x) * 6 + y) * wsz + w1) * wsz + w2) * DIMF;

        float4 xv = ((const float4*)(in + inIdx))[lane];
        float s  = xv.x + xv.y + xv.z + xv.w;
        float ss = xv.x*xv.x + xv.y*xv.y + xv.z*xv.z + xv.w*xv.w;
        #pragma unroll
        for (int off = 16; off > 0; off >>= 1) {
            s  += __shfl_xor_sync(FULL, s,  off);
            ss += __shfl_xor_sync(FULL, ss, off);
        }
        float mu   = s * (1.f / 128.f);
        float var  = ss * (1.f / 128.f) - mu * mu;
        float rstd = rsqrtf(var + 1e-5f);

        float xn[4];
        xn[0] = (xv.x - mu) * rstd * gm.x + bt.x;
        xn[1] = (xv.y - mu) * rstd * gm.y + bt.y;
        xn[2] = (xv.z - mu) * rstd * gm.z + bt.z;
        xn[3] = (xv.w - mu) * rstd * gm.w + bt.w;

        u64t acc0 = pack2(bi.x, bi.y), acc1 = pack2(bi.z, bi.w);
        #pragma unroll 8
        for (int sl = 0; sl < 32; ++sl) {
            #pragma unroll
            for (int jj = 0; jj < 4; ++jj) {
                float xk = __shfl_sync(FULL, xn[jj], sl);
                u64t xk2 = pack2(xk, xk);
                ulonglong2 w2 = Wsh2[(sl * 4 + jj) * 32 + lane];
                acc0 = fma2(xk2, w2.x, acc0);
                acc1 = fma2(xk2, w2.y, acc1);
            }
        }
        float ax, ay, az, aw;
        unpack2(acc0, ax, ay); unpack2(acc1, az, aw);
        ((float4*)(out + ((h * LWIN + l) * tokPerL + t) * 32 + dh))[0] =
            make_float4(ax, ay, az, aw);

        if (which == 0) {
            float sq = ax*ax + ay*ay + az*az + aw*aw;
            sq += __shfl_down_sync(FULL, sq, 4, 8);
            sq += __shfl_down_sync(FULL, sq, 2, 8);
            sq += __shfl_down_sync(FULL, sq, 1, 8);
            if ((lane & 7) == 0)
                SAL[(h * LWIN + l) * tokPerL + t] = sq;
        }
    }
}

// ---------------------------------------------------------------------------
// Kernel 2: keep top-1152 of 1536 saliencies per (h,l).
// ---------------------------------------------------------------------------
__global__ void qkeep_kernel()
{
    __shared__ unsigned keys[QN];
    __shared__ int cnts[2];
    __shared__ int wse[8];
    __shared__ int gtTot;
    const int tid = threadIdx.x, lane = tid & 31, wid = tid >> 5;
    const int row = blockIdx.x;
    const int base = tid * 6;

    for (int i = tid; i < QN; i += 256)
        keys[i] = f2key(SAL[row * QN + i]);
    if (tid < 2) cnts[tid] = 0;
    if (tid == 2) gtTot = 0;
    __syncthreads();

    const unsigned k0 = keys[base+0], k1 = keys[base+1], k2 = keys[base+2],
                   k3 = keys[base+3], k4 = keys[base+4], k5 = keys[base+5];

    unsigned T = 0;
    int exact = 0;
    for (int b = 31; b >= 0; --b) {
        unsigned cand = T | (1u << b);
        unsigned c = (k0>=cand)+(k1>=cand)+(k2>=cand)+(k3>=cand)+(k4>=cand)+(k5>=cand);
        c = __reduce_add_sync(FULL, c);
        if (lane == 0) atomicAdd(&cnts[b & 1], (int)c);
        __syncthreads();
        int tot = cnts[b & 1];
        if (tid == 0) cnts[(b & 1) ^ 1] = 0;
        if (tot >= KEEPQ) { T = cand; if (tot == KEEPQ) exact = 1; }
        __syncthreads();
        if (exact) break;
    }

    unsigned char* Qp = &QKEEP[row * QN + base];
    if (exact) {
        Qp[0] = (k0 >= T); Qp[1] = (k1 >= T); Qp[2] = (k2 >= T);
        Qp[3] = (k3 >= T); Qp[4] = (k4 >= T); Qp[5] = (k5 >= T);
    } else {
        int gtc = (k0>T)+(k1>T)+(k2>T)+(k3>T)+(k4>T)+(k5>T);
        int e0 = (k0==T), e1 = (k1==T), e2 = (k2==T),
            e3 = (k3==T), e4 = (k4==T), e5 = (k5==T);
        int eqc = e0+e1+e2+e3+e4+e5;
        unsigned g = __reduce_add_sync(FULL, (unsigned)gtc);
        if (lane == 0) atomicAdd(&gtTot, (int)g);
        int incl = eqc;
        #pragma unroll
        for (int off = 1; off < 32; off <<= 1) {
            int n = __shfl_up_sync(FULL, incl, off);
            if (lane >= off) incl += n;
        }
        if (lane == 31) wse[wid] = incl;
        __syncthreads();
        int before = 0;
        for (int w = 0; w < wid; ++w) before += wse[w];
        int myExcl = before + incl - eqc;
        int r = (KEEPQ - gtTot) - myExcl;
        int cum = 0;
        Qp[0] = (k0>T) || (e0 && cum < r); cum += e0;
        Qp[1] = (k1>T) || (e1 && cum < r); cum += e1;
        Qp[2] = (k2>T) || (e2 && cum < r); cum += e2;
        Qp[3] = (k3>T) || (e3 && cum < r); cum += e3;
        Qp[4] = (k4>T) || (e4 && cum < r); cum += e4;
        Qp[5] = (k5>T) || (e5 && cum < r);
    }
}

// ---------------------------------------------------------------------------
// Kernel 3: pruned-query result = mean(VH[0:96]) per (h,l).
// ---------------------------------------------------------------------------
__global__ void pmean_kernel()
{
    const int hl = blockIdx.x, d = threadIdx.x;
    float s = 0.f;
    for (int k = 0; k < TOPK; ++k) s += VH[(hl * KN + k) * 32 + d];
    PMEAN[hl * 32 + d] = s * (1.f / (float)TOPK);
}

// ---------------------------------------------------------------------------
// Kernel 4: attention. One block per (h,l), 512 threads. Warp = 4 queries,
// 12 k/lane. QK^T and AV use packed f32x2 FMA (2 MACs/issue). Lockstep
// top-96 bit-search with pair-packed counts, early exit on count==96.
// ---------------------------------------------------------------------------
__global__ void __launch_bounds__(512, 1) attn_kernel()
{
    extern __shared__ float sm[];
    float* Kt = sm;              // 32 x 388
    float* Vt = sm + 12416;      // 32 x 388
    float* AB = sm + 24832;      // 16 warps * 4 q * 384

    const int hl = blockIdx.x;
    const int tid = threadIdx.x, lane = tid & 31, wid = tid >> 5;

    for (int i = tid; i < KN * 32; i += 512) {
        int k = i >> 5, d = i & 31;
        Kt[d * 388 + k] = KH[hl * (KN * 32) + i];
        Vt[d * 388 + k] = VH[hl * (KN * 32) + i];
    }
    __syncthreads();

    const float pm = PMEAN[hl * 32 + lane];
    float* myAB = AB + wid * 1536;
    const unsigned lt = (1u << lane) - 1u;

    for (int g = wid; g < QN / 4; g += 16) {
        const int q0 = g * 4;
        float qreg[4]; int kp[4];
        #pragma unroll
        for (int qq = 0; qq < 4; ++qq) {
            qreg[qq] = QH[(hl * QN + q0 + qq) * 32 + lane] * SCALE_F;
            kp[qq]   = QKEEP[hl * QN + q0 + qq];
        }

        // packed accumulators: a2[qq][i] holds logits (2k per entry)
        union { u64t a2[4][6]; unsigned u[4][12]; } A;
        #pragma unroll
        for (int qq = 0; qq < 4; ++qq)
            #pragma unroll
            for (int i = 0; i < 6; ++i) A.a2[qq][i] = 0ull;

        // QK^T: lane owns k = lane*12 .. lane*12+11 (6 packed pairs)
        #pragma unroll 4
        for (int d = 0; d < 32; ++d) {
            const ulonglong2* kr = (const ulonglong2*)(Kt + d * 388 + lane * 12);
            ulonglong2 p0 = kr[0], p1 = kr[1], p2 = kr[2];
            u64t kv2[6] = {p0.x, p0.y, p1.x, p1.y, p2.x, p2.y};
            #pragma unroll
            for (int qq = 0; qq < 4; ++qq) {
                if (kp[qq]) {                       // warp-uniform
                    float qb = __shfl_sync(FULL, qreg[qq], d);
                    u64t qb2 = pack2(qb, qb);
                    #pragma unroll
                    for (int i = 0; i < 6; ++i)
                        A.a2[qq][i] = fma2(qb2, kv2[i], A.a2[qq][i]);
                }
            }
        }

        // sortable keys in place (kept queries only)
        #pragma unroll
        for (int qq = 0; qq < 4; ++qq)
            if (kp[qq]) {
                #pragma unroll
                for (int i = 0; i < 12; ++i)
                    A.u[qq][i] = bits2key(A.u[qq][i]);
            }

        // batched bitwise threshold search; counts packed 2-per-reduce
        unsigned T[4] = {0u, 0u, 0u, 0u};
        int act = (kp[0] ? 1 : 0) | (kp[1] ? 2 : 0) | (kp[2] ? 4 : 0) | (kp[3] ? 8 : 0);
        int exact = 0;
        for (int b = 31; b >= 0; --b) {
            int still = act & ~exact;
            if (!still) break;
            const unsigned bit = 1u << b;
            unsigned cand0 = T[0] | bit, cand1 = T[1] | bit,
                     cand2 = T[2] | bit, cand3 = T[3] | bit;
            unsigned p01 = 0, p23 = 0;
            #pragma unroll
            for (int i = 0; i < 12; ++i) {
                p01 += (A.u[0][i] >= cand0 ? 1u : 0u) | (A.u[1][i] >= cand1 ? 0x10000u : 0u);
                p23 += (A.u[2][i] >= cand2 ? 1u : 0u) | (A.u[3][i] >= cand3 ? 0x10000u : 0u);
            }
            p01 = __reduce_add_sync(FULL, p01);
            p23 = __reduce_add_sync(FULL, p23);
            unsigned c[4] = { p01 & 0xFFFFu, p01 >> 16, p23 & 0xFFFFu, p23 >> 16 };
            #pragma unroll
            for (int qq = 0; qq < 4; ++qq) {
                if (((still >> qq) & 1) && c[qq] >= (unsigned)TOPK) {
                    T[qq] |= bit;
                    if (c[qq] == (unsigned)TOPK) exact |= 1 << qq;
                }
            }
        }

        // keep mask + softmax per kept query
        #pragma unroll
        for (int qq = 0; qq < 4; ++qq) {
            if (!kp[qq]) continue;                  // warp-uniform
            bool keep[12];
            if ((exact >> qq) & 1) {
                #pragma unroll
                for (int i = 0; i < 12; ++i) keep[i] = (A.u[qq][i] >= T[qq]);
            } else {
                unsigned Tq = T[qq];
                unsigned cg = 0;
                #pragma unroll
                for (int i = 0; i < 12; ++i) cg += (A.u[qq][i] > Tq) ? 1u : 0u;
                cg = __reduce_add_sync(FULL, cg);
                int rem = (int)TOPK - (int)cg;
                int pre = 0;
                #pragma unroll
                for (int i = 0; i < 12; ++i) {
                    unsigned m = __ballot_sync(FULL, A.u[qq][i] == Tq);
                    pre += __popc(m & lt);
                }
                int cum = 0;
                #pragma unroll
                for (int i = 0; i < 12; ++i) {
                    bool eq = (A.u[qq][i] == Tq);
                    keep[i] = (A.u[qq][i] > Tq) || (eq && (pre + cum) < rem);
                    cum += eq ? 1 : 0;
                }
            }
            unsigned km = A.u[qq][0];
            #pragma unroll
            for (int i = 1; i < 12; ++i) km = max(km, A.u[qq][i]);
            #pragma unroll
            for (int off = 16; off > 0; off >>= 1)
                km = max(km, __shfl_xor_sync(FULL, km, off));
            float mx = key2f(km);

            float e[12]; float ssum = 0.f;
            #pragma unroll
            for (int i = 0; i < 12; ++i) {
                float ev = keep[i] ? __expf(key2f(A.u[qq][i]) - mx) : 0.f;
                e[i] = ev; ssum += ev;
            }
            #pragma unroll
            for (int off = 16; off > 0; off >>= 1)
                ssum += __shfl_xor_sync(FULL, ssum, off);
            float inv = 1.f / ssum;
            float4* dst = (float4*)(myAB + qq * 384 + lane * 12);
            dst[0] = make_float4(e[0]*inv, e[1]*inv, e[2]*inv,  e[3]*inv);
            dst[1] = make_float4(e[4]*inv, e[5]*inv, e[6]*inv,  e[7]*inv);
            dst[2] = make_float4(e[8]*inv, e[9]*inv, e[10]*inv, e[11]*inv);
        }
        __syncwarp();

        // AV: lane = output dim; packed f32x2 dot, V amortized over 4 queries
        u64t o2[4] = {0ull, 0ull, 0ull, 0ull};
        const ulonglong2* vr  = (const ulonglong2*)(Vt + lane * 388);
        const ulonglong2* a0p = (const ulonglong2*)(myAB);
        const ulonglong2* a1p = (const ulonglong2*)(myAB + 384);
        const ulonglong2* a2p = (const ulonglong2*)(myAB + 768);
        const ulonglong2* a3p = (const ulonglong2*)(myAB + 1152);
        #pragma unroll 4
        for (int c = 0; c < KN / 4; ++c) {
            ulonglong2 v2 = vr[c];
            ulonglong2 a;
            if (kp[0]) { a = a0p[c]; o2[0] = fma2(a.x, v2.x, o2[0]); o2[0] = fma2(a.y, v2.y, o2[0]); }
            if (kp[1]) { a = a1p[c]; o2[1] = fma2(a.x, v2.x, o2[1]); o2[1] = fma2(a.y, v2.y, o2[1]); }
            if (kp[2]) { a = a2p[c]; o2[2] = fma2(a.x, v2.x, o2[2]); o2[2] = fma2(a.y, v2.y, o2[2]); }
            if (kp[3]) { a = a3p[c]; o2[3] = fma2(a.x, v2.x, o2[3]); o2[3] = fma2(a.y, v2.y, o2[3]); }
        }
        __syncwarp();

        #pragma unroll
        for (int qq = 0; qq < 4; ++qq) {
            float lo, hi;
            unpack2(o2[qq], lo, hi);
            AO[(hl * QN + q0 + qq) * 32 + lane] = kp[qq] ? (lo + hi) : pm;
        }
    }
}

// ---------------------------------------------------------------------------
// Kernel 5: camera-mean -> output projection (packed f32x2) -> + bp + skip.
// ---------------------------------------------------------------------------
__global__ void final_kernel(const float* __restrict__ skip,
                             const float* __restrict__ Wp,
                             const float* __restrict__ bp,
                             float* __restrict__ outp)
{
    extern __shared__ float Wsh[];
    for (int i = threadIdx.x; i < 128 * 128 / 4; i += blockDim.x)
        ((float4*)Wsh)[i] = ((const float4*)Wp)[i];
    __syncthreads();

    const int lane = threadIdx.x & 31;
    const int wid  = threadIdx.x >> 5;
    const int nwarps = (blockDim.x >> 5) * gridDim.x;
    int gw = blockIdx.x * (blockDim.x >> 5) + wid;
    const ulonglong2* Wsh2 = (const ulonglong2*)Wsh;
    const float4 bi = ((const float4*)bp)[lane];
    const int h = lane >> 3, dbase = (lane & 7) * 4;

    for (int o = gw; o < LWIN * 256; o += nwarps) {
        int l = o >> 8, rr = o & 255;
        float4 ab = make_float4(0.f,0.f,0.f,0.f);
        #pragma unroll
        for (int n = 0; n < NCAM; ++n) {
            float4 t = ((const float4*)(AO + ((h * LWIN + l) * QN + n * 256 + rr) * 32 + dbase))[0];
            ab.x += t.x; ab.y += t.y; ab.z += t.z; ab.w += t.w;
        }
        const float inv6 = 1.f / 6.f;
        float xn[4] = {ab.x*inv6, ab.y*inv6, ab.z*inv6, ab.w*inv6};

        u64t acc0 = pack2(bi.x, bi.y), acc1 = pack2(bi.z, bi.w);
        #pragma unroll 8
        for (int sl = 0; sl < 32; ++sl) {
            #pragma unroll
            for (int jj = 0; jj < 4; ++jj) {
                float xk = __shfl_sync(FULL, xn[jj], sl);
                u64t xk2 = pack2(xk, xk);
                ulonglong2 w2 = Wsh2[(sl * 4 + jj) * 32 + lane];
                acc0 = fma2(xk2, w2.x, acc0);
                acc1 = fma2(xk2, w2.y, acc1);
            }
        }
        float ax, ay, az, aw;
        unpack2(acc0, ax, ay); unpack2(acc1, az, aw);
        float4 sk = ((const float4*)(skip + o * DIMF))[lane];
        ((float4*)(outp + o * DIMF))[lane] =
            make_float4(ax + sk.x, ay + sk.y, az + sk.z, aw + sk.w);
    }
}

// ---------------------------------------------------------------------------
// Inputs: 0 q, 1 k, 2 v, 3 skip, 4 logit_bias (dead), 5 g_q, 6 b_q, 7 g_k,
// 8 b_k, 9 g_v, 10 b_v, 11 Wq, 12 bq, 13 Wk, 14 bk, 15 Wv, 16 bv, 17 Wp, 18 bp
// ---------------------------------------------------------------------------
extern "C" void kernel_launch(void* const* d_in, const int* in_sizes, int n_in,
                              void* d_out, int out_size)
{
    const float* q    = (const float*)d_in[0];
    const float* k    = (const float*)d_in[1];
    const float* v    = (const float*)d_in[2];
    const float* skip = (const float*)d_in[3];
    const float* g_q  = (const float*)d_in[5];
    const float* b_q  = (const float*)d_in[6];
    const float* g_k  = (const float*)d_in[7];
    const float* b_k  = (const float*)d_in[8];
    const float* g_v  = (const float*)d_in[9];
    const float* b_v  = (const float*)d_in[10];
    const float* Wq   = (const float*)d_in[11];
    const float* bq   = (const float*)d_in[12];
    const float* Wk   = (const float*)d_in[13];
    const float* bk   = (const float*)d_in[14];
    const float* Wv   = (const float*)d_in[15];
    const float* bv   = (const float*)d_in[16];
    const float* Wp   = (const float*)d_in[17];
    const float* bp   = (const float*)d_in[18];
    float* outp = (float*)d_out;

    cudaFuncSetAttribute(proj_all_kernel, cudaFuncAttributeMaxDynamicSharedMemorySize, 65536);
    cudaFuncSetAttribute(attn_kernel,     cudaFuncAttributeMaxDynamicSharedMemorySize, 197632);
    cudaFuncSetAttribute(final_kernel,    cudaFuncAttributeMaxDynamicSharedMemorySize, 65536);

    proj_all_kernel<<<QBLK + KBLK + VBLK, 256, 65536>>>(
        q, k, v, g_q, b_q, g_k, b_k, g_v, b_v,
        Wq, bq, Wk, bk, Wv, bv);
    qkeep_kernel<<<HL, 256>>>();
    pmean_kernel<<<HL, 32>>>();
    attn_kernel<<<HL, 512, 197632>>>();
    final_kernel<<<148, 256, 65536>>>(skip, Wp, bp, outp);
}